// round 2
// baseline (speedup 1.0000x reference)
#include <cuda_runtime.h>
#include <math.h>

constexpr int TOK = 4096;   // B*N tokens
constexpr int C   = 768;
constexpr int C3  = 2304;
constexpr int MD  = 3072;
constexpr int NH  = 12;
constexpr int HD  = 64;
constexpr int SEQ = 1024;
constexpr int BH  = 48;     // B*NH

// ---------------- scratch (device globals; no allocation allowed) ----------
__device__ float g_h1[TOK * C];
__device__ float g_qkv[TOK * C3];
__device__ float g_attn[TOK * C];
__device__ float g_x1[TOK * C];
__device__ float g_h2[TOK * C];
__device__ float g_mid[TOK * MD];

// ---------------- LayerNorm: one block per row (768 cols, 256 thr) --------
__global__ void ln_kernel(const float* __restrict__ x, const float* __restrict__ g,
                          const float* __restrict__ b, float* __restrict__ out) {
    __shared__ float s1[256], s2[256];
    int row = blockIdx.x, t = threadIdx.x;
    const float* xr = x + (size_t)row * C;
    float v0 = xr[t], v1 = xr[t + 256], v2 = xr[t + 512];
    s1[t] = v0 + v1 + v2;
    s2[t] = v0 * v0 + v1 * v1 + v2 * v2;
    __syncthreads();
    for (int o = 128; o > 0; o >>= 1) {
        if (t < o) { s1[t] += s1[t + o]; s2[t] += s2[t + o]; }
        __syncthreads();
    }
    float mean = s1[0] * (1.0f / C);
    float var  = s2[0] * (1.0f / C) - mean * mean;
    float inv  = rsqrtf(var + 1e-5f);
    float* orow = out + (size_t)row * C;
    orow[t]       = (v0 - mean) * inv * g[t]       + b[t];
    orow[t + 256] = (v1 - mean) * inv * g[t + 256] + b[t + 256];
    orow[t + 512] = (v2 - mean) * inv * g[t + 512] + b[t + 512];
}

// ---------------- generic tiled SGEMM: C = A[M,K] @ B[K,N] + epilogue -----
// 64x64 tile, BK=16, 256 threads, 4x4 micro-tile.
template <bool BIAS, bool GELU_ACT, int NRES>
__global__ void gemm_kernel(const float* __restrict__ A, const float* __restrict__ B,
                            const float* __restrict__ bias, const float* __restrict__ r1,
                            const float* __restrict__ r2, float* __restrict__ Cout,
                            int N, int K) {
    __shared__ float As[16][68];   // [k][m], padded
    __shared__ float Bs[16][64];   // [k][n]
    int tid = threadIdx.x;
    int m0 = blockIdx.y * 64, n0 = blockIdx.x * 64;
    int arow = tid >> 2, akk = (tid & 3) * 4;
    int brow = tid >> 4, bcol = (tid & 15) * 4;
    int ty = tid >> 4, tx = tid & 15;
    float acc[4][4] = {};
    for (int k0 = 0; k0 < K; k0 += 16) {
        float4 av = *(const float4*)&A[(size_t)(m0 + arow) * K + k0 + akk];
        float4 bv = *(const float4*)&B[(size_t)(k0 + brow) * N + n0 + bcol];
        As[akk + 0][arow] = av.x; As[akk + 1][arow] = av.y;
        As[akk + 2][arow] = av.z; As[akk + 3][arow] = av.w;
        *(float4*)&Bs[brow][bcol] = bv;
        __syncthreads();
#pragma unroll
        for (int kk = 0; kk < 16; kk++) {
            float4 a4 = *(const float4*)&As[kk][ty * 4];
            float4 b4 = *(const float4*)&Bs[kk][tx * 4];
            float ar[4] = {a4.x, a4.y, a4.z, a4.w};
            float br[4] = {b4.x, b4.y, b4.z, b4.w};
#pragma unroll
            for (int i = 0; i < 4; i++)
#pragma unroll
                for (int j = 0; j < 4; j++) acc[i][j] += ar[i] * br[j];
        }
        __syncthreads();
    }
#pragma unroll
    for (int i = 0; i < 4; i++) {
        int row = m0 + ty * 4 + i;
#pragma unroll
        for (int j = 0; j < 4; j++) {
            int col = n0 + tx * 4 + j;
            float v = acc[i][j];
            if (BIAS) v += bias[col];
            if (GELU_ACT) v = 0.5f * v * (1.0f + erff(v * 0.70710678118654752f));
            size_t idx = (size_t)row * N + col;
            if (NRES >= 1) v += r1[idx];
            if (NRES >= 2) v += r2[idx];
            Cout[idx] = v;
        }
    }
}

// ---------------- fused flash attention ------------------------------------
// One CTA per (64-query tile, b*h). 256 threads, 4x4 micro-tile over 64x64.
// Online softmax in registers; K/V streamed in 64-wide tiles through smem.
// Dynamic smem: Qs[64][68] + KPs[64][68] + Vs[64][64] = 51200 bytes.
constexpr int ATTN_SMEM = (64 * 68 + 64 * 68 + 64 * 64) * 4;

__global__ void attn_kernel() {
    extern __shared__ float sm[];
    float (*Qs)[68]  = (float(*)[68])sm;              // Q^T: Qs[d][row]
    float (*KPs)[68] = (float(*)[68])(sm + 64 * 68);  // K^T: [d][kv]; then P: [row][kv]
    float (*Vs)[64]  = (float(*)[64])(sm + 2 * 64 * 68); // V: [kv][d]

    int tid = threadIdx.x;
    int bh = blockIdx.y, b = bh / NH, h = bh - b * NH;
    int q0 = blockIdx.x * 64;
    int ty = tid >> 4, tx = tid & 15;
    int arow = tid >> 2, akk = (tid & 3) * 4;   // transpose-load pattern
    int vrow = tid >> 4, vcol = (tid & 15) * 4; // row-load pattern

    const float* base = g_qkv + (size_t)b * SEQ * C3;
    const float* qb = base + h * HD;            // Q columns
    const float* kb = base + C + h * HD;        // K columns
    const float* vb = base + 2 * C + h * HD;    // V columns

    // load Q tile transposed: Qs[d][row]
#pragma unroll
    for (int k0 = 0; k0 < HD; k0 += 16) {
        float4 qv = *(const float4*)&qb[(size_t)(q0 + arow) * C3 + k0 + akk];
        Qs[k0 + akk + 0][arow] = qv.x; Qs[k0 + akk + 1][arow] = qv.y;
        Qs[k0 + akk + 2][arow] = qv.z; Qs[k0 + akk + 3][arow] = qv.w;
    }

    float acc_o[4][4] = {};
    float m_i[4] = {-1e30f, -1e30f, -1e30f, -1e30f};
    float l_i[4] = {};

    for (int kv0 = 0; kv0 < SEQ; kv0 += 64) {
        __syncthreads();   // previous iter's KPs/Vs reads done (also covers Q load, iter 0)
        // load K tile transposed: KPs[d][kv]
#pragma unroll
        for (int k0 = 0; k0 < HD; k0 += 16) {
            float4 kv = *(const float4*)&kb[(size_t)(kv0 + arow) * C3 + k0 + akk];
            KPs[k0 + akk + 0][arow] = kv.x; KPs[k0 + akk + 1][arow] = kv.y;
            KPs[k0 + akk + 2][arow] = kv.z; KPs[k0 + akk + 3][arow] = kv.w;
        }
        // load V tile: Vs[kv][d]
#pragma unroll
        for (int kk0 = 0; kk0 < 64; kk0 += 16) {
            *(float4*)&Vs[kk0 + vrow][vcol] =
                *(const float4*)&vb[(size_t)(kv0 + kk0 + vrow) * C3 + vcol];
        }
        __syncthreads();

        // S = Q K^T * 0.125
        float s[4][4] = {};
#pragma unroll
        for (int d = 0; d < HD; d++) {
            float4 a4 = *(const float4*)&Qs[d][ty * 4];
            float4 b4 = *(const float4*)&KPs[d][tx * 4];
            float ar[4] = {a4.x, a4.y, a4.z, a4.w};
            float br[4] = {b4.x, b4.y, b4.z, b4.w};
#pragma unroll
            for (int i = 0; i < 4; i++)
#pragma unroll
                for (int j = 0; j < 4; j++) s[i][j] += ar[i] * br[j];
        }

        // online softmax update (row reductions across the 16 tx lanes)
        float corr[4];
#pragma unroll
        for (int i = 0; i < 4; i++) {
            float mx = fmaxf(fmaxf(s[i][0], s[i][1]), fmaxf(s[i][2], s[i][3])) * 0.125f;
#pragma unroll
            for (int o = 8; o > 0; o >>= 1)
                mx = fmaxf(mx, __shfl_xor_sync(0xffffffffu, mx, o));
            float mn = fmaxf(m_i[i], mx);
            corr[i] = __expf(m_i[i] - mn);
            m_i[i] = mn;
            float rs = 0.f;
#pragma unroll
            for (int j = 0; j < 4; j++) {
                s[i][j] = __expf(s[i][j] * 0.125f - mn);
                rs += s[i][j];
            }
#pragma unroll
            for (int o = 8; o > 0; o >>= 1)
                rs += __shfl_xor_sync(0xffffffffu, rs, o);
            l_i[i] = l_i[i] * corr[i] + rs;
#pragma unroll
            for (int j = 0; j < 4; j++) acc_o[i][j] *= corr[i];
        }

        __syncthreads();   // all warps done reading KPs (as K)
        // store P: KPs[row][kv]  (float4 row stores, conflict-free)
#pragma unroll
        for (int i = 0; i < 4; i++)
            *(float4*)&KPs[ty * 4 + i][tx * 4] = make_float4(s[i][0], s[i][1], s[i][2], s[i][3]);
        __syncthreads();

        // O += P @ V   (P rows read as broadcast scalars)
#pragma unroll 8
        for (int kk = 0; kk < 64; kk++) {
            float4 b4 = *(const float4*)&Vs[kk][tx * 4];
            float br[4] = {b4.x, b4.y, b4.z, b4.w};
#pragma unroll
            for (int i = 0; i < 4; i++) {
                float a = KPs[ty * 4 + i][kk];
#pragma unroll
                for (int j = 0; j < 4; j++) acc_o[i][j] += a * br[j];
            }
        }
    }

    // final normalize + write [token, h*64+d]
#pragma unroll
    for (int i = 0; i < 4; i++) {
        float inv = 1.0f / l_i[i];
#pragma unroll
        for (int j = 0; j < 4; j++)
            g_attn[(size_t)(b * SEQ + q0 + ty * 4 + i) * C + h * HD + tx * 4 + j] =
                acc_o[i][j] * inv;
    }
}

// ---------------- launch ---------------------------------------------------
extern "C" void kernel_launch(void* const* d_in, const int* in_sizes, int n_in,
                              void* d_out, int out_size) {
    const float* x    = (const float*)d_in[0];
    const float* ln1g = (const float*)d_in[1];
    const float* ln1b = (const float*)d_in[2];
    const float* wqkv = (const float*)d_in[3];
    const float* wout = (const float*)d_in[4];
    const float* bout = (const float*)d_in[5];
    const float* ln2g = (const float*)d_in[6];
    const float* ln2b = (const float*)d_in[7];
    const float* w1   = (const float*)d_in[8];
    const float* b1   = (const float*)d_in[9];
    const float* w2   = (const float*)d_in[10];
    const float* b2   = (const float*)d_in[11];
    float* out = (float*)d_out;

    float *h1, *qkvp, *attnp, *x1p, *h2p, *midp;
    cudaGetSymbolAddress((void**)&h1,    g_h1);
    cudaGetSymbolAddress((void**)&qkvp,  g_qkv);
    cudaGetSymbolAddress((void**)&attnp, g_attn);
    cudaGetSymbolAddress((void**)&x1p,   g_x1);
    cudaGetSymbolAddress((void**)&h2p,   g_h2);
    cudaGetSymbolAddress((void**)&midp,  g_mid);

    cudaFuncSetAttribute(attn_kernel, cudaFuncAttributeMaxDynamicSharedMemorySize,
                         ATTN_SMEM);

    // 1) h = LN1(x)
    ln_kernel<<<TOK, 256>>>(x, ln1g, ln1b, h1);
    // 2) qkv = h @ w_qkv
    gemm_kernel<false, false, 0><<<dim3(C3 / 64, TOK / 64), 256>>>(
        h1, wqkv, nullptr, nullptr, nullptr, qkvp, C3, C);
    // 3) fused attention: softmax(QK^T/8) @ V
    attn_kernel<<<dim3(SEQ / 64, BH), 256, ATTN_SMEM>>>();
    // 4) x1 = x + h + attn @ w_out + b_out   (double residual)
    gemm_kernel<true, false, 2><<<dim3(C / 64, TOK / 64), 256>>>(
        attnp, wout, bout, x, h1, x1p, C, C);
    // 5) h2 = LN2(x1)
    ln_kernel<<<TOK, 256>>>(x1p, ln2g, ln2b, h2p);
    // 6) mid = gelu(h2 @ w1 + b1)
    gemm_kernel<true, true, 0><<<dim3(MD / 64, TOK / 64), 256>>>(
        h2p, w1, b1, nullptr, nullptr, midp, MD, C);
    // 7) out = x1 + mid @ w2 + b2
    gemm_kernel<true, false, 1><<<dim3(C / 64, TOK / 64), 256>>>(
        midp, w2, b2, x1p, nullptr, out, C, MD);
}

// round 3
// speedup vs baseline: 1.9617x; 1.9617x over previous
#include <cuda_runtime.h>
#include <math.h>
#include <stdint.h>

constexpr int TOK = 4096;   // B*N tokens
constexpr int C   = 768;
constexpr int C3  = 2304;
constexpr int MD  = 3072;
constexpr int NH  = 12;
constexpr int HD  = 64;
constexpr int SEQ = 1024;
constexpr int BH  = 48;     // B*NH

// ---------------- scratch (device globals; no allocation allowed) ----------
__device__ float g_h1[TOK * C];
__device__ float g_qkv[TOK * C3];
__device__ float g_attn[TOK * C];
__device__ float g_x1[TOK * C];
__device__ float g_h2[TOK * C];
__device__ float g_mid[TOK * MD];

__device__ __forceinline__ uint32_t f2tf(float x) {
    uint32_t r;
    asm("cvt.rna.tf32.f32 %0, %1;" : "=r"(r) : "f"(x));
    return r;
}

// ---------------- LayerNorm: one block per row (768 cols, 256 thr) --------
__global__ void ln_kernel(const float* __restrict__ x, const float* __restrict__ g,
                          const float* __restrict__ b, float* __restrict__ out) {
    __shared__ float s1[256], s2[256];
    int row = blockIdx.x, t = threadIdx.x;
    const float* xr = x + (size_t)row * C;
    float v0 = xr[t], v1 = xr[t + 256], v2 = xr[t + 512];
    s1[t] = v0 + v1 + v2;
    s2[t] = v0 * v0 + v1 * v1 + v2 * v2;
    __syncthreads();
    for (int o = 128; o > 0; o >>= 1) {
        if (t < o) { s1[t] += s1[t + o]; s2[t] += s2[t + o]; }
        __syncthreads();
    }
    float mean = s1[0] * (1.0f / C);
    float var  = s2[0] * (1.0f / C) - mean * mean;
    float inv  = rsqrtf(var + 1e-5f);
    float* orow = out + (size_t)row * C;
    orow[t]       = (v0 - mean) * inv * g[t]       + b[t];
    orow[t + 256] = (v1 - mean) * inv * g[t + 256] + b[t + 256];
    orow[t + 512] = (v2 - mean) * inv * g[t + 512] + b[t + 512];
}

// ---------------- TF32 tensor-core GEMM: C = A[M,K] @ B[K,N] + epilogue ----
// 128x128 CTA tile, BK=16, 256 threads = 8 warps (4 in M x 2 in N),
// warp tile 32x64, mma.m16n8k8 tf32. Double-buffered smem with a
// global->reg->smem software pipeline.
// As row stride 20, Bs row stride 136: both make fragment LDS conflict-free.
template <bool BIAS, bool GELU_ACT, int NRES>
__global__ __launch_bounds__(256) void gemm_tc(
    const float* __restrict__ A, const float* __restrict__ B,
    const float* __restrict__ bias, const float* __restrict__ r1,
    const float* __restrict__ r2, float* __restrict__ Cout, int N, int K) {
    __shared__ uint32_t As[2][128][20];
    __shared__ uint32_t Bs[2][16][136];
    const int tid = threadIdx.x;
    const int m0 = blockIdx.y * 128, n0 = blockIdx.x * 128;
    const int warp = tid >> 5, lane = tid & 31;
    const int wm = warp & 3, wn = warp >> 2;
    const int gid = lane >> 2, tig = lane & 3;

    const int arow = tid >> 2, acol = (tid & 3) * 4;     // A: rows arow, arow+64
    const int brow = tid >> 5, bcol = (tid & 31) * 4;    // B: rows brow, brow+8

    float acc[2][8][4] = {};
    float4 stA[2], stB[2];

    auto load_regs = [&](int k0) {
        stA[0] = *(const float4*)&A[(size_t)(m0 + arow) * K + k0 + acol];
        stA[1] = *(const float4*)&A[(size_t)(m0 + arow + 64) * K + k0 + acol];
        stB[0] = *(const float4*)&B[(size_t)(k0 + brow) * N + n0 + bcol];
        stB[1] = *(const float4*)&B[(size_t)(k0 + brow + 8) * N + n0 + bcol];
    };
    auto store_stage = [&](int s) {
#pragma unroll
        for (int r = 0; r < 2; r++) {
            uint4 ua = make_uint4(f2tf(stA[r].x), f2tf(stA[r].y), f2tf(stA[r].z), f2tf(stA[r].w));
            *(uint4*)&As[s][arow + r * 64][acol] = ua;
            uint4 ub = make_uint4(f2tf(stB[r].x), f2tf(stB[r].y), f2tf(stB[r].z), f2tf(stB[r].w));
            *(uint4*)&Bs[s][brow + r * 8][bcol] = ub;
        }
    };
    auto mma_stage = [&](int s) {
#pragma unroll
        for (int kk = 0; kk < 16; kk += 8) {
            uint32_t af[2][4], bf[8][2];
#pragma unroll
            for (int mt = 0; mt < 2; mt++) {
                int mr = wm * 32 + mt * 16 + gid;
                af[mt][0] = As[s][mr][kk + tig];
                af[mt][1] = As[s][mr + 8][kk + tig];
                af[mt][2] = As[s][mr][kk + tig + 4];
                af[mt][3] = As[s][mr + 8][kk + tig + 4];
            }
#pragma unroll
            for (int nt = 0; nt < 8; nt++) {
                int nc = wn * 64 + nt * 8 + gid;
                bf[nt][0] = Bs[s][kk + tig][nc];
                bf[nt][1] = Bs[s][kk + tig + 4][nc];
            }
#pragma unroll
            for (int mt = 0; mt < 2; mt++)
#pragma unroll
                for (int nt = 0; nt < 8; nt++)
                    asm volatile(
                        "mma.sync.aligned.m16n8k8.row.col.f32.tf32.tf32.f32 "
                        "{%0,%1,%2,%3}, {%4,%5,%6,%7}, {%8,%9}, {%0,%1,%2,%3};"
                        : "+f"(acc[mt][nt][0]), "+f"(acc[mt][nt][1]),
                          "+f"(acc[mt][nt][2]), "+f"(acc[mt][nt][3])
                        : "r"(af[mt][0]), "r"(af[mt][1]), "r"(af[mt][2]), "r"(af[mt][3]),
                          "r"(bf[nt][0]), "r"(bf[nt][1]));
        }
    };

    const int nk = K / 16;
    load_regs(0);
    store_stage(0);
    __syncthreads();
    for (int i = 0; i < nk; i++) {
        int s = i & 1;
        if (i + 1 < nk) load_regs((i + 1) * 16);
        mma_stage(s);
        if (i + 1 < nk) store_stage(s ^ 1);
        __syncthreads();
    }

    // epilogue
#pragma unroll
    for (int mt = 0; mt < 2; mt++) {
        int r0 = m0 + wm * 32 + mt * 16 + gid;
#pragma unroll
        for (int nt = 0; nt < 8; nt++) {
            int col = n0 + wn * 64 + nt * 8 + tig * 2;
#pragma unroll
            for (int half = 0; half < 2; half++) {
                int row = r0 + half * 8;
                float v0 = acc[mt][nt][half * 2 + 0];
                float v1 = acc[mt][nt][half * 2 + 1];
                if (BIAS) { v0 += bias[col]; v1 += bias[col + 1]; }
                if (GELU_ACT) {
                    v0 = 0.5f * v0 * (1.0f + erff(v0 * 0.70710678118654752f));
                    v1 = 0.5f * v1 * (1.0f + erff(v1 * 0.70710678118654752f));
                }
                size_t idx = (size_t)row * N + col;
                if (NRES >= 1) { v0 += r1[idx]; v1 += r1[idx + 1]; }
                if (NRES >= 2) { v0 += r2[idx]; v1 += r2[idx + 1]; }
                *(float2*)&Cout[idx] = make_float2(v0, v1);
            }
        }
    }
}

// ---------------- fused flash attention (FFMA, unchanged) ------------------
constexpr int ATTN_SMEM = (64 * 68 + 64 * 68 + 64 * 64) * 4;

__global__ void attn_kernel() {
    extern __shared__ float sm[];
    float (*Qs)[68]  = (float(*)[68])sm;
    float (*KPs)[68] = (float(*)[68])(sm + 64 * 68);
    float (*Vs)[64]  = (float(*)[64])(sm + 2 * 64 * 68);

    int tid = threadIdx.x;
    int bh = blockIdx.y, b = bh / NH, h = bh - b * NH;
    int q0 = blockIdx.x * 64;
    int ty = tid >> 4, tx = tid & 15;
    int arow = tid >> 2, akk = (tid & 3) * 4;
    int vrow = tid >> 4, vcol = (tid & 15) * 4;

    const float* base = g_qkv + (size_t)b * SEQ * C3;
    const float* qb = base + h * HD;
    const float* kb = base + C + h * HD;
    const float* vb = base + 2 * C + h * HD;

#pragma unroll
    for (int k0 = 0; k0 < HD; k0 += 16) {
        float4 qv = *(const float4*)&qb[(size_t)(q0 + arow) * C3 + k0 + akk];
        Qs[k0 + akk + 0][arow] = qv.x; Qs[k0 + akk + 1][arow] = qv.y;
        Qs[k0 + akk + 2][arow] = qv.z; Qs[k0 + akk + 3][arow] = qv.w;
    }

    float acc_o[4][4] = {};
    float m_i[4] = {-1e30f, -1e30f, -1e30f, -1e30f};
    float l_i[4] = {};

    for (int kv0 = 0; kv0 < SEQ; kv0 += 64) {
        __syncthreads();
#pragma unroll
        for (int k0 = 0; k0 < HD; k0 += 16) {
            float4 kv = *(const float4*)&kb[(size_t)(kv0 + arow) * C3 + k0 + akk];
            KPs[k0 + akk + 0][arow] = kv.x; KPs[k0 + akk + 1][arow] = kv.y;
            KPs[k0 + akk + 2][arow] = kv.z; KPs[k0 + akk + 3][arow] = kv.w;
        }
#pragma unroll
        for (int kk0 = 0; kk0 < 64; kk0 += 16) {
            *(float4*)&Vs[kk0 + vrow][vcol] =
                *(const float4*)&vb[(size_t)(kv0 + kk0 + vrow) * C3 + vcol];
        }
        __syncthreads();

        float s[4][4] = {};
#pragma unroll
        for (int d = 0; d < HD; d++) {
            float4 a4 = *(const float4*)&Qs[d][ty * 4];
            float4 b4 = *(const float4*)&KPs[d][tx * 4];
            float ar[4] = {a4.x, a4.y, a4.z, a4.w};
            float br[4] = {b4.x, b4.y, b4.z, b4.w};
#pragma unroll
            for (int i = 0; i < 4; i++)
#pragma unroll
                for (int j = 0; j < 4; j++) s[i][j] += ar[i] * br[j];
        }

        float corr[4];
#pragma unroll
        for (int i = 0; i < 4; i++) {
            float mx = fmaxf(fmaxf(s[i][0], s[i][1]), fmaxf(s[i][2], s[i][3])) * 0.125f;
#pragma unroll
            for (int o = 8; o > 0; o >>= 1)
                mx = fmaxf(mx, __shfl_xor_sync(0xffffffffu, mx, o));
            float mn = fmaxf(m_i[i], mx);
            corr[i] = __expf(m_i[i] - mn);
            m_i[i] = mn;
            float rs = 0.f;
#pragma unroll
            for (int j = 0; j < 4; j++) {
                s[i][j] = __expf(s[i][j] * 0.125f - mn);
                rs += s[i][j];
            }
#pragma unroll
            for (int o = 8; o > 0; o >>= 1)
                rs += __shfl_xor_sync(0xffffffffu, rs, o);
            l_i[i] = l_i[i] * corr[i] + rs;
#pragma unroll
            for (int j = 0; j < 4; j++) acc_o[i][j] *= corr[i];
        }

        __syncthreads();
#pragma unroll
        for (int i = 0; i < 4; i++)
            *(float4*)&KPs[ty * 4 + i][tx * 4] = make_float4(s[i][0], s[i][1], s[i][2], s[i][3]);
        __syncthreads();

#pragma unroll 8
        for (int kk = 0; kk < 64; kk++) {
            float4 b4 = *(const float4*)&Vs[kk][tx * 4];
            float br[4] = {b4.x, b4.y, b4.z, b4.w};
#pragma unroll
            for (int i = 0; i < 4; i++) {
                float a = KPs[ty * 4 + i][kk];
#pragma unroll
                for (int j = 0; j < 4; j++) acc_o[i][j] += a * br[j];
            }
        }
    }

#pragma unroll
    for (int i = 0; i < 4; i++) {
        float inv = 1.0f / l_i[i];
#pragma unroll
        for (int j = 0; j < 4; j++)
            g_attn[(size_t)(b * SEQ + q0 + ty * 4 + i) * C + h * HD + tx * 4 + j] =
                acc_o[i][j] * inv;
    }
}

// ---------------- launch ---------------------------------------------------
extern "C" void kernel_launch(void* const* d_in, const int* in_sizes, int n_in,
                              void* d_out, int out_size) {
    const float* x    = (const float*)d_in[0];
    const float* ln1g = (const float*)d_in[1];
    const float* ln1b = (const float*)d_in[2];
    const float* wqkv = (const float*)d_in[3];
    const float* wout = (const float*)d_in[4];
    const float* bout = (const float*)d_in[5];
    const float* ln2g = (const float*)d_in[6];
    const float* ln2b = (const float*)d_in[7];
    const float* w1   = (const float*)d_in[8];
    const float* b1   = (const float*)d_in[9];
    const float* w2   = (const float*)d_in[10];
    const float* b2   = (const float*)d_in[11];
    float* out = (float*)d_out;

    float *h1, *qkvp, *attnp, *x1p, *h2p, *midp;
    cudaGetSymbolAddress((void**)&h1,    g_h1);
    cudaGetSymbolAddress((void**)&qkvp,  g_qkv);
    cudaGetSymbolAddress((void**)&attnp, g_attn);
    cudaGetSymbolAddress((void**)&x1p,   g_x1);
    cudaGetSymbolAddress((void**)&h2p,   g_h2);
    cudaGetSymbolAddress((void**)&midp,  g_mid);

    cudaFuncSetAttribute(attn_kernel, cudaFuncAttributeMaxDynamicSharedMemorySize,
                         ATTN_SMEM);

    // 1) h = LN1(x)
    ln_kernel<<<TOK, 256>>>(x, ln1g, ln1b, h1);
    // 2) qkv = h @ w_qkv
    gemm_tc<false, false, 0><<<dim3(C3 / 128, TOK / 128), 256>>>(
        h1, wqkv, nullptr, nullptr, nullptr, qkvp, C3, C);
    // 3) fused attention: softmax(QK^T/8) @ V
    attn_kernel<<<dim3(SEQ / 64, BH), 256, ATTN_SMEM>>>();
    // 4) x1 = x + h + attn @ w_out + b_out   (double residual)
    gemm_tc<true, false, 2><<<dim3(C / 128, TOK / 128), 256>>>(
        attnp, wout, bout, x, h1, x1p, C, C);
    // 5) h2 = LN2(x1)
    ln_kernel<<<TOK, 256>>>(x1p, ln2g, ln2b, h2p);
    // 6) mid = gelu(h2 @ w1 + b1)
    gemm_tc<true, true, 0><<<dim3(MD / 128, TOK / 128), 256>>>(
        h2p, w1, b1, nullptr, nullptr, midp, MD, C);
    // 7) out = x1 + mid @ w2 + b2
    gemm_tc<true, false, 1><<<dim3(C / 128, TOK / 128), 256>>>(
        midp, w2, b2, x1p, nullptr, out, C, MD);
}

// round 5
// speedup vs baseline: 2.2461x; 1.1450x over previous
#include <cuda_runtime.h>
#include <math.h>
#include <stdint.h>

constexpr int TOK = 4096;   // B*N tokens
constexpr int C   = 768;
constexpr int C3  = 2304;
constexpr int MD  = 3072;
constexpr int NH  = 12;
constexpr int HD  = 64;
constexpr int SEQ = 1024;
constexpr int BH  = 48;     // B*NH

// ---------------- scratch (device globals; no allocation allowed) ----------
__device__ float g_h1[TOK * C];
__device__ float g_qkv[TOK * C3];
__device__ float g_attn[TOK * C];
__device__ float g_x1[TOK * C];
__device__ float g_h2[TOK * C];
__device__ float g_mid[TOK * MD];

#define CP_ASYNC16(dst, src) \
    asm volatile("cp.async.cg.shared.global [%0], [%1], 16;\n" :: "r"(dst), "l"(src))
#define CP_COMMIT() asm volatile("cp.async.commit_group;\n" ::)
#define CP_WAIT2()  asm volatile("cp.async.wait_group 2;\n" ::)

// ---------------- LayerNorm: one block per row (768 cols, 256 thr) --------
__global__ void ln_kernel(const float* __restrict__ x, const float* __restrict__ g,
                          const float* __restrict__ b, float* __restrict__ out) {
    __shared__ float s1[256], s2[256];
    int row = blockIdx.x, t = threadIdx.x;
    const float* xr = x + (size_t)row * C;
    float v0 = xr[t], v1 = xr[t + 256], v2 = xr[t + 512];
    s1[t] = v0 + v1 + v2;
    s2[t] = v0 * v0 + v1 * v1 + v2 * v2;
    __syncthreads();
    for (int o = 128; o > 0; o >>= 1) {
        if (t < o) { s1[t] += s1[t + o]; s2[t] += s2[t + o]; }
        __syncthreads();
    }
    float mean = s1[0] * (1.0f / C);
    float var  = s2[0] * (1.0f / C) - mean * mean;
    float inv  = rsqrtf(var + 1e-5f);
    float* orow = out + (size_t)row * C;
    orow[t]       = (v0 - mean) * inv * g[t]       + b[t];
    orow[t + 256] = (v1 - mean) * inv * g[t + 256] + b[t + 256];
    orow[t + 512] = (v2 - mean) * inv * g[t + 512] + b[t + 512];
}

// ---------------- TF32 tensor-core GEMM, cp.async 4-stage pipeline ---------
// 128x128 CTA tile, BK=16, 256 threads = 8 warps (4 in M x 2 in N),
// warp tile 32x64, mma.m16n8k8 tf32 fed raw fp32 bits (HW truncation).
// As[s][m][k] stride 20, Bs[s][k][n] stride 136 (conflict-free fragment LDS).
constexpr int STAGES = 4;
constexpr int A_STRIDE = 20;
constexpr int B_STRIDE = 136;
constexpr int A_STAGE_W = 128 * A_STRIDE;          // words per A stage
constexpr int B_STAGE_W = 16 * B_STRIDE;           // words per B stage
constexpr int GEMM_SMEM = (STAGES * (A_STAGE_W + B_STAGE_W)) * 4;  // 75776 B

template <bool BIAS, bool GELU_ACT, int NRES>
__global__ __launch_bounds__(256, 2) void gemm_tc(
    const float* __restrict__ A, const float* __restrict__ B,
    const float* __restrict__ bias, const float* __restrict__ r1,
    const float* __restrict__ r2, float* __restrict__ Cout, int N, int K) {
    extern __shared__ uint32_t smem[];
    uint32_t* AsBase = smem;                               // [STAGES][128][20]
    uint32_t* BsBase = smem + STAGES * A_STAGE_W;          // [STAGES][16][136]

    const int tid = threadIdx.x;
    const int m0 = blockIdx.y * 128, n0 = blockIdx.x * 128;
    const int warp = tid >> 5, lane = tid & 31;
    const int wm = warp & 3, wn = warp >> 2;
    const int gid = lane >> 2, tig = lane & 3;

    const int arow = tid >> 2, acol = (tid & 3) * 4;     // A: rows arow, arow+64
    const int brow = tid >> 5, bcol = (tid & 31) * 4;    // B: rows brow, brow+8

    const float* agp = A + (size_t)(m0 + arow) * K + acol;
    const float* bgp = B + (size_t)brow * N + n0 + bcol;
    const uint32_t da0 = (uint32_t)__cvta_generic_to_shared(
        AsBase + (size_t)arow * A_STRIDE + acol);
    const uint32_t db0 = (uint32_t)__cvta_generic_to_shared(
        BsBase + (size_t)brow * B_STRIDE + bcol);

    float acc[2][8][4] = {};

    auto issue_stage = [&](int s, int k0) {
        uint32_t da = da0 + s * (A_STAGE_W * 4);
        const float* ap = agp + k0;
        CP_ASYNC16(da, ap);
        CP_ASYNC16(da + 64 * A_STRIDE * 4, ap + (size_t)64 * K);
        uint32_t db = db0 + s * (B_STAGE_W * 4);
        const float* bp = bgp + (size_t)k0 * N;
        CP_ASYNC16(db, bp);
        CP_ASYNC16(db + 8 * B_STRIDE * 4, bp + (size_t)8 * N);
    };

    const uint32_t* Asm = AsBase;
    const uint32_t* Bsm = BsBase;

    auto mma_stage = [&](int s) {
        const uint32_t* As = Asm + s * A_STAGE_W;
        const uint32_t* Bs = Bsm + s * B_STAGE_W;
#pragma unroll
        for (int kk = 0; kk < 16; kk += 8) {
            uint32_t af[2][4], bf[8][2];
#pragma unroll
            for (int mt = 0; mt < 2; mt++) {
                int mr = wm * 32 + mt * 16 + gid;
                const uint32_t* ar = As + mr * A_STRIDE + kk + tig;
                af[mt][0] = ar[0];
                af[mt][1] = ar[8 * A_STRIDE];
                af[mt][2] = ar[4];
                af[mt][3] = ar[8 * A_STRIDE + 4];
            }
#pragma unroll
            for (int nt = 0; nt < 8; nt++) {
                int nc = wn * 64 + nt * 8 + gid;
                const uint32_t* br = Bs + (kk + tig) * B_STRIDE + nc;
                bf[nt][0] = br[0];
                bf[nt][1] = br[4 * B_STRIDE];
            }
#pragma unroll
            for (int mt = 0; mt < 2; mt++)
#pragma unroll
                for (int nt = 0; nt < 8; nt++)
                    asm volatile(
                        "mma.sync.aligned.m16n8k8.row.col.f32.tf32.tf32.f32 "
                        "{%0,%1,%2,%3}, {%4,%5,%6,%7}, {%8,%9}, {%0,%1,%2,%3};"
                        : "+f"(acc[mt][nt][0]), "+f"(acc[mt][nt][1]),
                          "+f"(acc[mt][nt][2]), "+f"(acc[mt][nt][3])
                        : "r"(af[mt][0]), "r"(af[mt][1]), "r"(af[mt][2]), "r"(af[mt][3]),
                          "r"(bf[nt][0]), "r"(bf[nt][1]));
        }
    };

    const int nk = K / 16;
    // prologue: fill stages 0..2
#pragma unroll
    for (int s = 0; s < STAGES - 1; s++) {
        issue_stage(s, s * 16);
        CP_COMMIT();
    }
    for (int i = 0; i < nk; i++) {
        CP_WAIT2();
        __syncthreads();
        int kn = (i + STAGES - 1) * 16;
        if (kn < K) issue_stage((i + STAGES - 1) & (STAGES - 1), kn);
        CP_COMMIT();
        mma_stage(i & (STAGES - 1));
    }

    // epilogue
#pragma unroll
    for (int mt = 0; mt < 2; mt++) {
        int r0 = m0 + wm * 32 + mt * 16 + gid;
#pragma unroll
        for (int nt = 0; nt < 8; nt++) {
            int col = n0 + wn * 64 + nt * 8 + tig * 2;
#pragma unroll
            for (int half = 0; half < 2; half++) {
                int row = r0 + half * 8;
                float v0 = acc[mt][nt][half * 2 + 0];
                float v1 = acc[mt][nt][half * 2 + 1];
                if (BIAS) { v0 += bias[col]; v1 += bias[col + 1]; }
                if (GELU_ACT) {
                    v0 = 0.5f * v0 * (1.0f + erff(v0 * 0.70710678118654752f));
                    v1 = 0.5f * v1 * (1.0f + erff(v1 * 0.70710678118654752f));
                }
                size_t idx = (size_t)row * N + col;
                if (NRES >= 1) { v0 += r1[idx]; v1 += r1[idx + 1]; }
                if (NRES >= 2) { v0 += r2[idx]; v1 += r2[idx + 1]; }
                *(float2*)&Cout[idx] = make_float2(v0, v1);
            }
        }
    }
}

// ---------------- fused flash attention (FFMA, unchanged) ------------------
constexpr int ATTN_SMEM = (64 * 68 + 64 * 68 + 64 * 64) * 4;

__global__ void attn_kernel() {
    extern __shared__ float sm[];
    float (*Qs)[68]  = (float(*)[68])sm;
    float (*KPs)[68] = (float(*)[68])(sm + 64 * 68);
    float (*Vs)[64]  = (float(*)[64])(sm + 2 * 64 * 68);

    int tid = threadIdx.x;
    int bh = blockIdx.y, b = bh / NH, h = bh - b * NH;
    int q0 = blockIdx.x * 64;
    int ty = tid >> 4, tx = tid & 15;
    int arow = tid >> 2, akk = (tid & 3) * 4;
    int vrow = tid >> 4, vcol = (tid & 15) * 4;

    const float* base = g_qkv + (size_t)b * SEQ * C3;
    const float* qb = base + h * HD;
    const float* kb = base + C + h * HD;
    const float* vb = base + 2 * C + h * HD;

#pragma unroll
    for (int k0 = 0; k0 < HD; k0 += 16) {
        float4 qv = *(const float4*)&qb[(size_t)(q0 + arow) * C3 + k0 + akk];
        Qs[k0 + akk + 0][arow] = qv.x; Qs[k0 + akk + 1][arow] = qv.y;
        Qs[k0 + akk + 2][arow] = qv.z; Qs[k0 + akk + 3][arow] = qv.w;
    }

    float acc_o[4][4] = {};
    float m_i[4] = {-1e30f, -1e30f, -1e30f, -1e30f};
    float l_i[4] = {};

    for (int kv0 = 0; kv0 < SEQ; kv0 += 64) {
        __syncthreads();
#pragma unroll
        for (int k0 = 0; k0 < HD; k0 += 16) {
            float4 kv = *(const float4*)&kb[(size_t)(kv0 + arow) * C3 + k0 + akk];
            KPs[k0 + akk + 0][arow] = kv.x; KPs[k0 + akk + 1][arow] = kv.y;
            KPs[k0 + akk + 2][arow] = kv.z; KPs[k0 + akk + 3][arow] = kv.w;
        }
#pragma unroll
        for (int kk0 = 0; kk0 < 64; kk0 += 16) {
            *(float4*)&Vs[kk0 + vrow][vcol] =
                *(const float4*)&vb[(size_t)(kv0 + kk0 + vrow) * C3 + vcol];
        }
        __syncthreads();

        float s[4][4] = {};
#pragma unroll
        for (int d = 0; d < HD; d++) {
            float4 a4 = *(const float4*)&Qs[d][ty * 4];
            float4 b4 = *(const float4*)&KPs[d][tx * 4];
            float ar[4] = {a4.x, a4.y, a4.z, a4.w};
            float br[4] = {b4.x, b4.y, b4.z, b4.w};
#pragma unroll
            for (int i = 0; i < 4; i++)
#pragma unroll
                for (int j = 0; j < 4; j++) s[i][j] += ar[i] * br[j];
        }

        float corr[4];
#pragma unroll
        for (int i = 0; i < 4; i++) {
            float mx = fmaxf(fmaxf(s[i][0], s[i][1]), fmaxf(s[i][2], s[i][3])) * 0.125f;
#pragma unroll
            for (int o = 8; o > 0; o >>= 1)
                mx = fmaxf(mx, __shfl_xor_sync(0xffffffffu, mx, o));
            float mn = fmaxf(m_i[i], mx);
            corr[i] = __expf(m_i[i] - mn);
            m_i[i] = mn;
            float rs = 0.f;
#pragma unroll
            for (int j = 0; j < 4; j++) {
                s[i][j] = __expf(s[i][j] * 0.125f - mn);
                rs += s[i][j];
            }
#pragma unroll
            for (int o = 8; o > 0; o >>= 1)
                rs += __shfl_xor_sync(0xffffffffu, rs, o);
            l_i[i] = l_i[i] * corr[i] + rs;
#pragma unroll
            for (int j = 0; j < 4; j++) acc_o[i][j] *= corr[i];
        }

        __syncthreads();
#pragma unroll
        for (int i = 0; i < 4; i++)
            *(float4*)&KPs[ty * 4 + i][tx * 4] = make_float4(s[i][0], s[i][1], s[i][2], s[i][3]);
        __syncthreads();

#pragma unroll 8
        for (int kk = 0; kk < 64; kk++) {
            float4 b4 = *(const float4*)&Vs[kk][tx * 4];
            float br[4] = {b4.x, b4.y, b4.z, b4.w};
#pragma unroll
            for (int i = 0; i < 4; i++) {
                float a = KPs[ty * 4 + i][kk];
#pragma unroll
                for (int j = 0; j < 4; j++) acc_o[i][j] += a * br[j];
            }
        }
    }

#pragma unroll
    for (int i = 0; i < 4; i++) {
        float inv = 1.0f / l_i[i];
#pragma unroll
        for (int j = 0; j < 4; j++)
            g_attn[(size_t)(b * SEQ + q0 + ty * 4 + i) * C + h * HD + tx * 4 + j] =
                acc_o[i][j] * inv;
    }
}

// ---------------- launch ---------------------------------------------------
extern "C" void kernel_launch(void* const* d_in, const int* in_sizes, int n_in,
                              void* d_out, int out_size) {
    const float* x    = (const float*)d_in[0];
    const float* ln1g = (const float*)d_in[1];
    const float* ln1b = (const float*)d_in[2];
    const float* wqkv = (const float*)d_in[3];
    const float* wout = (const float*)d_in[4];
    const float* bout = (const float*)d_in[5];
    const float* ln2g = (const float*)d_in[6];
    const float* ln2b = (const float*)d_in[7];
    const float* w1   = (const float*)d_in[8];
    const float* b1   = (const float*)d_in[9];
    const float* w2   = (const float*)d_in[10];
    const float* b2   = (const float*)d_in[11];
    float* out = (float*)d_out;

    float *h1, *qkvp, *attnp, *x1p, *h2p, *midp;
    cudaGetSymbolAddress((void**)&h1,    g_h1);
    cudaGetSymbolAddress((void**)&qkvp,  g_qkv);
    cudaGetSymbolAddress((void**)&attnp, g_attn);
    cudaGetSymbolAddress((void**)&x1p,   g_x1);
    cudaGetSymbolAddress((void**)&h2p,   g_h2);
    cudaGetSymbolAddress((void**)&midp,  g_mid);

    cudaFuncSetAttribute(attn_kernel, cudaFuncAttributeMaxDynamicSharedMemorySize,
                         ATTN_SMEM);
    cudaFuncSetAttribute(gemm_tc<false, false, 0>,
                         cudaFuncAttributeMaxDynamicSharedMemorySize, GEMM_SMEM);
    cudaFuncSetAttribute(gemm_tc<true, false, 2>,
                         cudaFuncAttributeMaxDynamicSharedMemorySize, GEMM_SMEM);
    cudaFuncSetAttribute(gemm_tc<true, true, 0>,
                         cudaFuncAttributeMaxDynamicSharedMemorySize, GEMM_SMEM);
    cudaFuncSetAttribute(gemm_tc<true, false, 1>,
                         cudaFuncAttributeMaxDynamicSharedMemorySize, GEMM_SMEM);

    // 1) h = LN1(x)
    ln_kernel<<<TOK, 256>>>(x, ln1g, ln1b, h1);
    // 2) qkv = h @ w_qkv
    gemm_tc<false, false, 0><<<dim3(C3 / 128, TOK / 128), 256, GEMM_SMEM>>>(
        h1, wqkv, nullptr, nullptr, nullptr, qkvp, C3, C);
    // 3) fused attention: softmax(QK^T/8) @ V
    attn_kernel<<<dim3(SEQ / 64, BH), 256, ATTN_SMEM>>>();
    // 4) x1 = x + h + attn @ w_out + b_out   (double residual)
    gemm_tc<true, false, 2><<<dim3(C / 128, TOK / 128), 256, GEMM_SMEM>>>(
        attnp, wout, bout, x, h1, x1p, C, C);
    // 5) h2 = LN2(x1)
    ln_kernel<<<TOK, 256>>>(x1p, ln2g, ln2b, h2p);
    // 6) mid = gelu(h2 @ w1 + b1)
    gemm_tc<true, true, 0><<<dim3(MD / 128, TOK / 128), 256, GEMM_SMEM>>>(
        h2p, w1, b1, nullptr, nullptr, midp, MD, C);
    // 7) out = x1 + mid @ w2 + b2
    gemm_tc<true, false, 1><<<dim3(C / 128, TOK / 128), 256, GEMM_SMEM>>>(
        midp, w2, b2, x1p, nullptr, out, C, MD);
}